// round 1
// baseline (speedup 1.0000x reference)
#include <cuda_runtime.h>
#include <cuda_bf16.h>

#define DD 512      // feature dim (fixed for this problem)
#define MT 128      // rows (queries) per CTA
#define NT 128      // codes per chunk
#define KS 8        // k-step for the smem-tiled GEMM

// Scratch (no device allocation allowed -> static device globals)
__device__ float g_cn[8192];     // ||c_j||^2
__device__ int   g_ids[32768];   // argmin ids

// ---------------------------------------------------------------------------
// Kernel 0: per-code squared norms. One warp per code.
// ---------------------------------------------------------------------------
__global__ void cnorm_kernel(const float* __restrict__ cb) {
    int warp = (blockIdx.x * blockDim.x + threadIdx.x) >> 5;
    int lane = threadIdx.x & 31;
    const float4* p = (const float4*)(cb + (size_t)warp * DD);
    float s = 0.f;
#pragma unroll
    for (int i = 0; i < DD / 4 / 32; i++) {   // 4 iterations
        float4 v = p[lane + 32 * i];
        s += v.x * v.x + v.y * v.y + v.z * v.z + v.w * v.w;
    }
#pragma unroll
    for (int o = 16; o; o >>= 1) s += __shfl_xor_sync(0xffffffffu, s, o);
    if (lane == 0) g_cn[warp] = s;
}

// ---------------------------------------------------------------------------
// Kernel 1: fused fp32 GEMM + running argmin.
// CTA = 128 rows of x; loops over all K codes in chunks of 128.
// score m_j = ||c_j||^2 - 2 * (x . c_j)  (||x||^2 dropped: constant per row)
// ---------------------------------------------------------------------------
__global__ void __launch_bounds__(256)
qgemm_argmin_kernel(const float* __restrict__ x, const float* __restrict__ cb,
                    float* __restrict__ out, int N, int K)
{
    __shared__ __align__(16) float As[2][KS][MT];   // 8 KB
    __shared__ __align__(16) float Bs[2][KS][NT];   // 8 KB

    const int tid  = threadIdx.x;
    const int tx   = tid & 15;          // code sub-tile
    const int ty   = tid >> 4;          // row sub-tile
    const int row0 = blockIdx.x * MT;

    // global->smem loader mapping: 256 threads, each loads one float4 of A and B
    const int lr = tid >> 1;            // 0..127 (row / code within tile)
    const int lk = (tid & 1) << 2;      // 0 or 4 (k offset of the float4)

    const float* Aptr = x + (size_t)(row0 + lr) * DD + lk;

    float best_v[8];
    int   best_i[8];
#pragma unroll
    for (int i = 0; i < 8; i++) { best_v[i] = 3.0e38f; best_i[i] = 0; }

    float acc[8][8];

    auto compute = [&](int b) {
#pragma unroll
        for (int k = 0; k < KS; k++) {
            float a[8], c[8];
            *(float4*)(a)     = *(const float4*)(&As[b][k][ty * 8]);
            *(float4*)(a + 4) = *(const float4*)(&As[b][k][ty * 8 + 4]);
            *(float4*)(c)     = *(const float4*)(&Bs[b][k][tx * 8]);
            *(float4*)(c + 4) = *(const float4*)(&Bs[b][k][tx * 8 + 4]);
#pragma unroll
            for (int i = 0; i < 8; i++)
#pragma unroll
                for (int j = 0; j < 8; j++)
                    acc[i][j] = fmaf(a[i], c[j], acc[i][j]);
        }
    };

    for (int nc = 0; nc < K; nc += NT) {
        const float* Bptr = cb + (size_t)(nc + lr) * DD + lk;

#pragma unroll
        for (int i = 0; i < 8; i++)
#pragma unroll
            for (int j = 0; j < 8; j++) acc[i][j] = 0.f;

        // prefetch k-step 0
        float4 av = *(const float4*)(Aptr);
        float4 bv = *(const float4*)(Bptr);
        int buf = 0;
        As[0][lk + 0][lr] = av.x; As[0][lk + 1][lr] = av.y;
        As[0][lk + 2][lr] = av.z; As[0][lk + 3][lr] = av.w;
        Bs[0][lk + 0][lr] = bv.x; Bs[0][lk + 1][lr] = bv.y;
        Bs[0][lk + 2][lr] = bv.z; Bs[0][lk + 3][lr] = bv.w;
        __syncthreads();

#pragma unroll 1
        for (int kk = KS; kk < DD; kk += KS) {
            av = *(const float4*)(Aptr + kk);
            bv = *(const float4*)(Bptr + kk);
            compute(buf);
            buf ^= 1;
            As[buf][lk + 0][lr] = av.x; As[buf][lk + 1][lr] = av.y;
            As[buf][lk + 2][lr] = av.z; As[buf][lk + 3][lr] = av.w;
            Bs[buf][lk + 0][lr] = bv.x; Bs[buf][lk + 1][lr] = bv.y;
            Bs[buf][lk + 2][lr] = bv.z; Bs[buf][lk + 3][lr] = bv.w;
            __syncthreads();
        }
        compute(buf);   // last k-step

        // per-chunk argmin update (registers only)
#pragma unroll
        for (int j = 0; j < 8; j++) {
            int   code = nc + tx * 8 + j;
            float cnj  = g_cn[code];
#pragma unroll
            for (int i = 0; i < 8; i++) {
                float m = fmaf(-2.f, acc[i][j], cnj);
                if (m < best_v[i]) { best_v[i] = m; best_i[i] = code; }
            }
        }
        // no extra sync needed: next chunk writes buf 0, whose last reader
        // finished before the final in-loop __syncthreads of this chunk.
    }

    // cross-thread argmin reduction (16 partials per row), reusing smem
    __syncthreads();
    float* rv = &As[0][0][0];          // 16*128 floats (fits: As = 2048 floats)
    int*   ri = (int*)&Bs[0][0][0];    // 16*128 ints
#pragma unroll
    for (int i = 0; i < 8; i++) {
        rv[tx * MT + ty * 8 + i] = best_v[i];
        ri[tx * MT + ty * 8 + i] = best_i[i];
    }
    __syncthreads();
    if (tid < MT) {
        float bv2 = rv[tid];
        int   bi  = ri[tid];
#pragma unroll 1
        for (int t = 1; t < 16; t++) {
            float v  = rv[t * MT + tid];
            int   ii = ri[t * MT + tid];
            if (v < bv2 || (v == bv2 && ii < bi)) { bv2 = v; bi = ii; }
        }
        int row = row0 + tid;
        g_ids[row] = bi;
        out[(size_t)N * DD + row] = (float)bi;   // ids output (as float)
    }
}

// ---------------------------------------------------------------------------
// Kernel 2: gather emb_out = codebook[id], loss = 1.25 * sum((x - emb)^2)
// One CTA (128 threads) per row; float4 per thread.
// ---------------------------------------------------------------------------
__global__ void gather_loss_kernel(const float* __restrict__ x,
                                   const float* __restrict__ cb,
                                   float* __restrict__ out, int N)
{
    int row = blockIdx.x;
    int t   = threadIdx.x;              // 0..127
    int id  = g_ids[row];

    float4 xv = ((const float4*)(x  + (size_t)row * DD))[t];
    float4 cv = ((const float4*)(cb + (size_t)id  * DD))[t];
    ((float4*)(out + (size_t)row * DD))[t] = cv;

    float dx = xv.x - cv.x, dy = xv.y - cv.y, dz = xv.z - cv.z, dw = xv.w - cv.w;
    float s = dx * dx + dy * dy + dz * dz + dw * dw;
#pragma unroll
    for (int o = 16; o; o >>= 1) s += __shfl_xor_sync(0xffffffffu, s, o);

    __shared__ float ws[4];
    if ((t & 31) == 0) ws[t >> 5] = s;
    __syncthreads();
    if (t == 0) {
        float tot = ws[0] + ws[1] + ws[2] + ws[3];
        out[(size_t)N * DD + N + row] = 1.25f * tot;   // emb_loss + 0.25*query_loss
    }
}

// ---------------------------------------------------------------------------
extern "C" void kernel_launch(void* const* d_in, const int* in_sizes, int n_in,
                              void* d_out, int out_size)
{
    const float* x  = (const float*)d_in[0];
    const float* cb = (const float*)d_in[1];
    float* out = (float*)d_out;

    int N = in_sizes[0] / DD;   // 32768
    int K = in_sizes[1] / DD;   // 8192

    cnorm_kernel<<<K / 8, 256>>>(cb);
    qgemm_argmin_kernel<<<N / MT, 256>>>(x, cb, out, N, K);
    gather_loss_kernel<<<N, 128>>>(x, cb, out, N);
}

// round 3
// speedup vs baseline: 2.9598x; 2.9598x over previous
#include <cuda_runtime.h>
#include <cuda_fp16.h>
#include <cstdint>

#define DD    512
#define NROWS 32768
#define KCODE 8192
#define TAU   0.004f

// ---------------- device scratch ----------------
__device__ __align__(1024) __half g_xh[NROWS * DD];
__device__ __align__(1024) __half g_xl[NROWS * DD];
__device__ __align__(1024) __half g_ch[KCODE * DD];
__device__ __align__(1024) __half g_cl[KCODE * DD];
__device__ float              g_cn[KCODE];
__device__ int                g_ids[NROWS];
__device__ int                g_flagcnt;
__device__ int                g_flaglist[NROWS];
__device__ unsigned char      g_flagged[NROWS];
__device__ unsigned long long g_fix[NROWS];

// ---------------- helpers ----------------
__device__ __forceinline__ uint32_t smem_u32(const void* p) {
    uint32_t a;
    asm("{ .reg .u64 t; cvta.to.shared.u64 t, %1; cvt.u32.u64 %0, t; }" : "=r"(a) : "l"(p));
    return a;
}
__device__ __forceinline__ void ldsm4(uint32_t* r, uint32_t addr) {
    asm volatile("ldmatrix.sync.aligned.m8n8.x4.shared.b16 {%0,%1,%2,%3}, [%4];"
                 : "=r"(r[0]), "=r"(r[1]), "=r"(r[2]), "=r"(r[3]) : "r"(addr));
}
__device__ __forceinline__ void mma16816(float* c, const uint32_t* a, const uint32_t* b) {
    asm volatile("mma.sync.aligned.m16n8k16.row.col.f32.f16.f16.f32 "
                 "{%0,%1,%2,%3}, {%4,%5,%6,%7}, {%8,%9}, {%0,%1,%2,%3};"
                 : "+f"(c[0]), "+f"(c[1]), "+f"(c[2]), "+f"(c[3])
                 : "r"(a[0]), "r"(a[1]), "r"(a[2]), "r"(a[3]), "r"(b[0]), "r"(b[1]));
}
__device__ __forceinline__ void cp16(uint32_t dst, const void* src) {
    asm volatile("cp.async.cg.shared.global [%0], [%1], 16;" :: "r"(dst), "l"(src));
}
__device__ __forceinline__ void cp_commit() { asm volatile("cp.async.commit_group;" ::: "memory"); }
__device__ __forceinline__ void cp_wait1()  { asm volatile("cp.async.wait_group 1;" ::: "memory"); }
__device__ __forceinline__ void cp_wait0()  { asm volatile("cp.async.wait_group 0;" ::: "memory"); }

// smem layout: [0,32K) code norms; [32K, 32K+2*64K) pipeline stages
#define S_STAGE0  32768
#define STAGE_SZ  65536
#define SMEM_MAIN (S_STAGE0 + 2 * STAGE_SZ)   // 163840

// ---------------- kernel 0: fp16 hi/lo split ----------------
__global__ void split_kernel(const float* __restrict__ src,
                             __half* __restrict__ hi, __half* __restrict__ lo, int n4)
{
    int i = blockIdx.x * blockDim.x + threadIdx.x;
    if (i >= n4) return;
    float4 v = ((const float4*)src)[i];
    __half h0 = __float2half_rn(v.x), h1 = __float2half_rn(v.y);
    __half h2 = __float2half_rn(v.z), h3 = __float2half_rn(v.w);
    __half l0 = __float2half_rn(v.x - __half2float(h0));
    __half l1 = __float2half_rn(v.y - __half2float(h1));
    __half l2 = __float2half_rn(v.z - __half2float(h2));
    __half l3 = __float2half_rn(v.w - __half2float(h3));
    ((__half2*)hi)[i * 2 + 0] = __half2(h0, h1);
    ((__half2*)hi)[i * 2 + 1] = __half2(h2, h3);
    ((__half2*)lo)[i * 2 + 0] = __half2(l0, l1);
    ((__half2*)lo)[i * 2 + 1] = __half2(l2, l3);
}

// ---------------- kernel 1: code norms ----------------
__global__ void cnorm_kernel(const float* __restrict__ cb) {
    int w = (blockIdx.x * blockDim.x + threadIdx.x) >> 5;
    int lane = threadIdx.x & 31;
    const float4* p = (const float4*)(cb + (size_t)w * DD);
    float s = 0.f;
#pragma unroll
    for (int i = 0; i < 4; i++) {
        float4 v = p[lane + 32 * i];
        s += v.x * v.x + v.y * v.y + v.z * v.z + v.w * v.w;
    }
#pragma unroll
    for (int o = 16; o; o >>= 1) s += __shfl_xor_sync(0xffffffffu, s, o);
    if (lane == 0) g_cn[w] = s;
}

// ---------------- kernel 2: HMMA 3-pass GEMM + fused argmin ----------------
__global__ void __launch_bounds__(256, 1)
vq_main()
{
    extern __shared__ char smem[];
    const uint32_t sb = smem_u32(smem);
    float* cn_s = (float*)smem;

    const int tid  = threadIdx.x;
    const int lane = tid & 31;
    const int warp = tid >> 5;
    const int wm   = warp >> 1;       // 0..3  (32-row band)
    const int wn   = warp & 1;        // 0..1  (64-col band)
    const int row0 = blockIdx.x * 128;

    for (int i = tid; i < KCODE; i += 256) cn_s[i] = g_cn[i];

    // per-thread ldmatrix address components
    const int arow = wm * 32 + (lane & 15);          // A row within tile
    const int ak   = lane >> 4;                      // A k-block (0/1)
    const int arw  = arow & 7;
    const int nrow = wn * 64 + ((lane >> 4) << 3) + (lane & 7);  // B n within tile
    const int bk   = (lane >> 3) & 1;                // B k-block
    const int nrw  = nrow & 7;

    float acc[2][8][4];
    float bb[4], bb2[4];
    int   bi[4];
#pragma unroll
    for (int k = 0; k < 4; k++) { bb[k] = 3.0e38f; bb2[k] = 3.0e38f; bi[k] = 0; }

    // issue cp.async loads for flattened step t (chunk = t>>3, kslab = t&7)
    auto issue = [&](int t) {
        const int c = t >> 3, ks = t & 7;
        const uint32_t st = sb + S_STAGE0 + (t & 1) * STAGE_SZ;
        const size_t koff = (size_t)ks * 64;
#pragma unroll
        for (int i = 0; i < 4; i++) {
            const int idx = tid + i * 256;
            const int r = idx >> 3, sg = idx & 7;
            const uint32_t off = r * 128 + ((sg ^ (r & 7)) << 4);
            const size_t ao = (size_t)(row0 + r) * DD + koff + sg * 8;
            const size_t bo = (size_t)(c * 128 + r) * DD + koff + sg * 8;
            cp16(st + off,         g_xh + ao);
            cp16(st + 16384 + off, g_xl + ao);
            cp16(st + 32768 + off, g_ch + bo);
            cp16(st + 49152 + off, g_cl + bo);
        }
        cp_commit();
    };

    issue(0);
#pragma unroll 1
    for (int t = 0; t < 512; t++) {
        if (t < 511) { issue(t + 1); cp_wait1(); }
        else         { cp_wait0(); }
        __syncthreads();

        if ((t & 7) == 0) {
#pragma unroll
            for (int mt = 0; mt < 2; mt++)
#pragma unroll
                for (int nt = 0; nt < 8; nt++)
#pragma unroll
                    for (int q = 0; q < 4; q++) acc[mt][nt][q] = 0.f;
        }

        // compute this 64-dim k-slab
        {
            const uint32_t st  = sb + S_STAGE0 + (t & 1) * STAGE_SZ;
            const uint32_t aAh = st, aAl = st + 16384, aBh = st + 32768, aBl = st + 49152;
#pragma unroll
            for (int kq = 0; kq < 4; kq++) {
                const int ksg = kq * 2;
                uint32_t ah[8], al[8], bh[16], bl[16];
#pragma unroll
                for (int mt = 0; mt < 2; mt++) {
                    const uint32_t offA = (arow + mt * 16) * 128 + (((ksg + ak) ^ arw) << 4);
                    ldsm4(ah + 4 * mt, aAh + offA);
                    ldsm4(al + 4 * mt, aAl + offA);
                }
#pragma unroll
                for (int p = 0; p < 4; p++) {
                    const uint32_t offB = (nrow + p * 16) * 128 + (((ksg + bk) ^ nrw) << 4);
                    ldsm4(bh + 4 * p, aBh + offB);
                    ldsm4(bl + 4 * p, aBl + offB);
                }
#pragma unroll
                for (int mt = 0; mt < 2; mt++)
#pragma unroll
                    for (int nt = 0; nt < 8; nt++) {
                        mma16816(acc[mt][nt], ah + 4 * mt, bh + 2 * nt);
                        mma16816(acc[mt][nt], ah + 4 * mt, bl + 2 * nt);
                        mma16816(acc[mt][nt], al + 4 * mt, bh + 2 * nt);
                    }
            }
        }

        if ((t & 7) == 7) {
            // chunk epilogue: fold scores into running best/best2
            const int c   = t >> 3;
            const int cb0 = (c << 7) + wn * 64 + ((lane & 3) << 1);
#pragma unroll
            for (int mt = 0; mt < 2; mt++)
#pragma unroll
                for (int nt = 0; nt < 8; nt++) {
                    const int cc = cb0 + nt * 8;
                    const float n0 = cn_s[cc], n1 = cn_s[cc + 1];
                    float m;
                    const int k0 = mt * 2, k1 = mt * 2 + 1;
                    m = fmaf(-2.f, acc[mt][nt][0], n0);
                    if (m < bb2[k0]) { if (m < bb[k0]) { bb2[k0] = bb[k0]; bb[k0] = m; bi[k0] = cc; } else bb2[k0] = m; }
                    m = fmaf(-2.f, acc[mt][nt][1], n1);
                    if (m < bb2[k0]) { if (m < bb[k0]) { bb2[k0] = bb[k0]; bb[k0] = m; bi[k0] = cc + 1; } else bb2[k0] = m; }
                    m = fmaf(-2.f, acc[mt][nt][2], n0);
                    if (m < bb2[k1]) { if (m < bb[k1]) { bb2[k1] = bb[k1]; bb[k1] = m; bi[k1] = cc; } else bb2[k1] = m; }
                    m = fmaf(-2.f, acc[mt][nt][3], n1);
                    if (m < bb2[k1]) { if (m < bb[k1]) { bb2[k1] = bb[k1]; bb[k1] = m; bi[k1] = cc + 1; } else bb2[k1] = m; }
                }
        }
        __syncthreads();
    }

    // ---- cross-thread reduction: 8 candidate slots per row ----
    float* rv  = (float*)(smem + S_STAGE0);
    float* rv2 = rv + 1024;
    int*   ri  = (int*)(rv2 + 1024);
    const int slot = wn * 4 + (lane & 3);
#pragma unroll
    for (int k = 0; k < 4; k++) {
        const int lr = wm * 32 + (k >> 1) * 16 + (lane >> 2) + (k & 1) * 8;
        rv [lr * 8 + slot] = bb[k];
        rv2[lr * 8 + slot] = bb2[k];
        ri [lr * 8 + slot] = bi[k];
    }
    __syncthreads();
    if (tid < 128) {
        float b1 = rv[tid * 8], b2 = rv2[tid * 8];
        int   i1 = ri[tid * 8];
#pragma unroll
        for (int s = 1; s < 8; s++) {
            const float v = rv[tid * 8 + s], v2 = rv2[tid * 8 + s];
            const int   ii = ri[tid * 8 + s];
            if (v < b1)       { b2 = fminf(b1, v2); b1 = v; i1 = ii; }
            else if (v == b1) { if (ii < i1) i1 = ii; b2 = fminf(b2, fminf(v, v2)); }
            else              { b2 = fminf(b2, v); }
        }
        const int grow = row0 + tid;
        g_ids[grow] = i1;
        if (b2 - b1 < TAU) {
            int p = atomicAdd(&g_flagcnt, 1);
            g_flaglist[p] = grow;
            g_flagged[grow] = 1;
            g_fix[grow] = 0xFFFFFFFFFFFFFFFFull;
        }
    }
}

// ---------------- kernel 3: exact fp32 fixup for flagged rows ----------------
__global__ void __launch_bounds__(256, 1)
fixup_kernel(const float* __restrict__ x, const float* __restrict__ cb)
{
    const int cnt = g_flagcnt;
    if (cnt == 0) return;
    extern __shared__ float cs[];                  // 64 codes x 512 = 128 KB
    const int b   = blockIdx.x;
    const int tid = threadIdx.x;
    const int lane = tid & 31, warp = tid >> 5;
    {
        const float4* src = (const float4*)(cb + (size_t)b * 64 * DD);
        float4* dst = (float4*)cs;
        for (int i = tid; i < 64 * 128; i += 256) dst[i] = src[i];
    }
    __syncthreads();
    const int code_l = tid >> 2;
    const int part   = tid & 3;
    __shared__ unsigned long long wmin[8];
    for (int r = 0; r < cnt; r++) {
        const int row = g_flaglist[r];
        const float4* xr = (const float4*)(x + (size_t)row * DD) + part * 32;
        const float4* cr = (const float4*)(cs + code_l * DD) + part * 32;
        float s = 0.f;
#pragma unroll 8
        for (int i = 0; i < 32; i++) {
            float4 a = xr[i], c = cr[i];
            float d0 = a.x - c.x, d1 = a.y - c.y, d2 = a.z - c.z, d3 = a.w - c.w;
            s += d0 * d0 + d1 * d1 + d2 * d2 + d3 * d3;
        }
        s += __shfl_xor_sync(0xffffffffu, s, 1);
        s += __shfl_xor_sync(0xffffffffu, s, 2);
        unsigned long long pk =
            (((unsigned long long)__float_as_uint(s)) << 32) | (unsigned)(b * 64 + code_l);
#pragma unroll
        for (int o = 4; o < 32; o <<= 1) {
            unsigned lo = (unsigned)pk, hi = (unsigned)(pk >> 32);
            unsigned olo = __shfl_xor_sync(0xffffffffu, lo, o);
            unsigned ohi = __shfl_xor_sync(0xffffffffu, hi, o);
            unsigned long long opk = (((unsigned long long)ohi) << 32) | olo;
            if (opk < pk) pk = opk;
        }
        if (lane == 0) wmin[warp] = pk;
        __syncthreads();
        if (tid == 0) {
            unsigned long long m = wmin[0];
#pragma unroll
            for (int w = 1; w < 8; w++) if (wmin[w] < m) m = wmin[w];
            atomicMin(&g_fix[row], m);
        }
        __syncthreads();
    }
}

// ---------------- kernel 4: gather + ids + loss ----------------
__global__ void gather_loss_kernel(const float* __restrict__ x,
                                   const float* __restrict__ cb,
                                   float* __restrict__ out, int N)
{
    const int row = blockIdx.x;
    const int t   = threadIdx.x;
    const int id  = g_flagged[row] ? (int)(unsigned)(g_fix[row] & 0xffffffffu)
                                   : g_ids[row];
    float4 xv = ((const float4*)(x  + (size_t)row * DD))[t];
    float4 cv = ((const float4*)(cb + (size_t)id  * DD))[t];
    ((float4*)(out + (size_t)row * DD))[t] = cv;
    float dx = xv.x - cv.x, dy = xv.y - cv.y, dz = xv.z - cv.z, dw = xv.w - cv.w;
    float s = dx * dx + dy * dy + dz * dz + dw * dw;
#pragma unroll
    for (int o = 16; o; o >>= 1) s += __shfl_xor_sync(0xffffffffu, s, o);
    __shared__ float ws[4];
    if ((t & 31) == 0) ws[t >> 5] = s;
    __syncthreads();
    if (t == 0) out[(size_t)N * DD + N + row] = 1.25f * (ws[0] + ws[1] + ws[2] + ws[3]);
    if (t == 32) out[(size_t)N * DD + row] = (float)id;
}

// ---------------- host ----------------
extern "C" void kernel_launch(void* const* d_in, const int* in_sizes, int n_in,
                              void* d_out, int out_size)
{
    const float* x  = (const float*)d_in[0];
    const float* cb = (const float*)d_in[1];
    float* out = (float*)d_out;
    const int N = in_sizes[0] / DD;
    const int K = in_sizes[1] / DD;

    void *p_xh, *p_xl, *p_ch, *p_cl, *p_cnt, *p_flg;
    cudaGetSymbolAddress(&p_xh, g_xh);
    cudaGetSymbolAddress(&p_xl, g_xl);
    cudaGetSymbolAddress(&p_ch, g_ch);
    cudaGetSymbolAddress(&p_cl, g_cl);
    cudaGetSymbolAddress(&p_cnt, g_flagcnt);
    cudaGetSymbolAddress(&p_flg, g_flagged);

    static bool attr_done = false;
    if (!attr_done) {
        cudaFuncSetAttribute(vq_main, cudaFuncAttributeMaxDynamicSharedMemorySize, SMEM_MAIN);
        cudaFuncSetAttribute(fixup_kernel, cudaFuncAttributeMaxDynamicSharedMemorySize, 64 * DD * 4);
        attr_done = true;
    }

    cudaMemsetAsync(p_cnt, 0, sizeof(int));
    cudaMemsetAsync(p_flg, 0, N);

    const int n4x = N * DD / 4, n4c = K * DD / 4;
    split_kernel<<<(n4x + 255) / 256, 256>>>(x,  (__half*)p_xh, (__half*)p_xl, n4x);
    split_kernel<<<(n4c + 255) / 256, 256>>>(cb, (__half*)p_ch, (__half*)p_cl, n4c);
    cnorm_kernel<<<K / 8, 256>>>(cb);
    vq_main<<<N / 128, 256, SMEM_MAIN>>>();
    fixup_kernel<<<K / 64, 256, 64 * DD * 4>>>(x, cb);
    gather_loss_kernel<<<N, 128>>>(x, cb, out, N);
}